// round 2
// baseline (speedup 1.0000x reference)
#include <cuda_runtime.h>

#define IN_D 256
#define RU   128
#define OD   64
#define NB   2048
#define DDIM 32896
#define NS   9
#define HCONST 0.5f
#define EPS_C  1e-8f
#define LN_EPS_C 1e-5f

typedef unsigned long long ull;

// ---------------- device scratch (allocation-free) ----------------
__device__ float g_S  [IN_D*RU];    // H/sigma^2 + eps
__device__ float g_CS [IN_D*RU];    // centers * scale
__device__ float g_K2 [RU];         // sum_i c^2 * scale
__device__ float g_WgT[DDIM*OD];    // gamma[d]*W[o][d], stored [d][o]
__device__ float g_G  [OD];         // sum_d gamma*W
__device__ float g_Bc [OD];         // sum_d beta*W + bias
__device__ float g_fs [NB*RU];      // frs * rstd
__device__ float g_c0 [NB];         // -mu * rstd
__device__ float g_Part[NS*NB*OD];  // split-K partials

// ---------------- packed f32x2 helpers ----------------
__device__ __forceinline__ ull pk2(float x){
    unsigned u = __float_as_uint(x);
    ull r; asm("mov.b64 %0, {%1, %1};" : "=l"(r) : "r"(u)); return r;
}
__device__ __forceinline__ void fma2(ull &d, ull a, ull b){
    asm("fma.rn.f32x2 %0, %1, %2, %0;" : "+l"(d) : "l"(a), "l"(b));
}
__device__ __forceinline__ void unpk(ull v, float &lo, float &hi){
    unsigned ulo, uhi;
    asm("mov.b64 {%0, %1}, %2;" : "=r"(ulo), "=r"(uhi) : "l"(v));
    lo = __uint_as_float(ulo); hi = __uint_as_float(uhi);
}

// ---------------- k0: rule constants ----------------
__global__ void k0_rules(const float* __restrict__ centers, const float* __restrict__ sigmas){
    int i = blockIdx.x*256 + threadIdx.x;
    if (i < IN_D*RU){
        float sg = sigmas[i];
        float s  = HCONST/(sg*sg) + EPS_C;
        g_S[i]  = s;
        g_CS[i] = centers[i]*s;
    }
}

__global__ void k0_k2c(const float* __restrict__ centers, const float* __restrict__ sigmas){
    __shared__ float red[64];
    int r = blockIdx.x, tid = threadIdx.x;
    float p = 0.f;
    for (int i = tid; i < IN_D; i += 64){
        float c = centers[i*RU + r], sg = sigmas[i*RU + r];
        float s = HCONST/(sg*sg) + EPS_C;
        p += c*c*s;
    }
    red[tid] = p; __syncthreads();
    for (int s2 = 32; s2 > 0; s2 >>= 1){
        if (tid < s2) red[tid] += red[tid+s2];
        __syncthreads();
    }
    if (tid == 0) g_K2[r] = red[0];
}

// ---------------- k0: WgT = (gamma * W)^T via tiled transpose ----------------
__global__ void k0_wgt(const float* __restrict__ W, const float* __restrict__ gamma){
    __shared__ float T[64][65];
    int tid = threadIdx.x;
    int d0  = blockIdx.x * 64;   // 514 blocks * 64 = 32896
    #pragma unroll
    for (int j = 0; j < 4; ++j){
        int q = tid + j*256;
        int o = q >> 4, f = (q & 15)*4;
        float4 v = *(const float4*)(W + (size_t)o*DDIM + d0 + f);
        T[o][f+0]=v.x; T[o][f+1]=v.y; T[o][f+2]=v.z; T[o][f+3]=v.w;
    }
    __syncthreads();
    #pragma unroll
    for (int j = 0; j < 4; ++j){
        int q = tid + j*256;
        int dd = q >> 4, g4 = (q & 15)*4;
        int d = d0 + dd;
        float ga = gamma[d];
        float4 ov;
        ov.x = T[g4+0][dd]*ga; ov.y = T[g4+1][dd]*ga;
        ov.z = T[g4+2][dd]*ga; ov.w = T[g4+3][dd]*ga;
        *(float4*)(g_WgT + (size_t)d*OD + g4) = ov;
    }
}

// ---------------- k0: G[o], Bc[o] ----------------
__global__ void k0_gb(const float* __restrict__ W, const float* __restrict__ gamma,
                      const float* __restrict__ beta, const float* __restrict__ bias){
    __shared__ float r1[256], r2[256];
    int o = blockIdx.x, tid = threadIdx.x;
    float sg = 0.f, sb = 0.f;
    for (int d = tid; d < DDIM; d += 256){
        float w = W[(size_t)o*DDIM + d];
        sg += gamma[d]*w;
        sb += beta[d]*w;
    }
    r1[tid] = sg; r2[tid] = sb; __syncthreads();
    for (int s = 128; s > 0; s >>= 1){
        if (tid < s){ r1[tid] += r1[tid+s]; r2[tid] += r2[tid+s]; }
        __syncthreads();
    }
    if (tid == 0){ g_G[o] = r1[0]; g_Bc[o] = r2[0] + bias[o]; }
}

// ---------------- k1: firing levels + softmax + closed-form LN stats ----------------
// 128 threads, 16 batch rows per CTA. Warp wg owns b = b0 + wg*4 + bi;
// lane owns rule pairs {2*lane, 2*lane+1} and {2*lane+64, 2*lane+65}.
__global__ __launch_bounds__(128,2) void k1_frs(const float* __restrict__ X){
    extern __shared__ float sm1[];
    float* Xs = sm1;             // [256][17]  (X transposed: [i][b])
    float* Ss = sm1 + 256*17;    // [32][128]
    float* Cs = Ss  + 32*128;    // [32][128]
    __shared__ float K2s[RU];
    const int tid  = threadIdx.x;
    const int b0   = blockIdx.x * 16;
    const int lane = tid & 31, wg = tid >> 5;
    if (tid < RU) K2s[tid] = g_K2[tid];
    for (int q = tid; q < 16*64; q += 128){
        int bb = q >> 6, i4 = (q & 63)*4;
        float4 v = *(const float4*)(X + (size_t)(b0+bb)*IN_D + i4);
        Xs[(i4+0)*17+bb]=v.x; Xs[(i4+1)*17+bb]=v.y;
        Xs[(i4+2)*17+bb]=v.z; Xs[(i4+3)*17+bb]=v.w;
    }
    ull A1p[4][2], A2p[4][2];
    #pragma unroll
    for (int bi = 0; bi < 4; ++bi){
        A1p[bi][0]=0ull; A1p[bi][1]=0ull; A2p[bi][0]=0ull; A2p[bi][1]=0ull;
    }
    for (int c = 0; c < 8; ++c){
        __syncthreads();
        for (int q = tid; q < 32*32; q += 128){
            int row = q >> 5, col4 = (q & 31)*4;
            *(float4*)(Ss + row*RU + col4) = *(const float4*)(g_S  + (size_t)(c*32+row)*RU + col4);
            *(float4*)(Cs + row*RU + col4) = *(const float4*)(g_CS + (size_t)(c*32+row)*RU + col4);
        }
        __syncthreads();
        #pragma unroll 4
        for (int k = 0; k < 32; ++k){
            int i = c*32 + k;
            float x0 = Xs[i*17 + wg*4 + 0];
            float x1 = Xs[i*17 + wg*4 + 1];
            float x2 = Xs[i*17 + wg*4 + 2];
            float x3 = Xs[i*17 + wg*4 + 3];
            ull xx0 = pk2(x0*x0), xx1 = pk2(x1*x1), xx2 = pk2(x2*x2), xx3 = pk2(x3*x3);
            ull xp0 = pk2(x0),    xp1 = pk2(x1),    xp2 = pk2(x2),    xp3 = pk2(x3);
            #pragma unroll
            for (int jp = 0; jp < 2; ++jp){
                ull s2 = *(const ull*)(Ss + k*RU + 2*lane + 64*jp);
                ull c2 = *(const ull*)(Cs + k*RU + 2*lane + 64*jp);
                fma2(A1p[0][jp], xx0, s2); fma2(A1p[1][jp], xx1, s2);
                fma2(A1p[2][jp], xx2, s2); fma2(A1p[3][jp], xx3, s2);
                fma2(A2p[0][jp], xp0, c2); fma2(A2p[1][jp], xp1, c2);
                fma2(A2p[2][jp], xp2, c2); fma2(A2p[3][jp], xp3, c2);
            }
        }
    }
    #pragma unroll
    for (int bi = 0; bi < 4; ++bi){
        float sx = 0.f, sxx = 0.f;
        #pragma unroll
        for (int t = 0; t < 8; ++t){
            float x = Xs[(lane + 32*t)*17 + wg*4 + bi];
            sx += x; sxx += x*x;
        }
        #pragma unroll
        for (int off = 16; off; off >>= 1){
            sx  += __shfl_xor_sync(0xffffffffu, sx,  off);
            sxx += __shfl_xor_sync(0xffffffffu, sxx, off);
        }
        float lg[4], e[4];
        #pragma unroll
        for (int jp = 0; jp < 2; ++jp){
            float a1l,a1h,a2l,a2h;
            unpk(A1p[bi][jp], a1l, a1h);
            unpk(A2p[bi][jp], a2l, a2h);
            int r = 2*lane + 64*jp;
            lg[2*jp+0] = -(a1l - 2.f*a2l + K2s[r+0]) * (1.f/256.f);
            lg[2*jp+1] = -(a1h - 2.f*a2h + K2s[r+1]) * (1.f/256.f);
        }
        float m = fmaxf(fmaxf(lg[0],lg[1]), fmaxf(lg[2],lg[3]));
        #pragma unroll
        for (int off = 16; off; off >>= 1)
            m = fmaxf(m, __shfl_xor_sync(0xffffffffu, m, off));
        float se = 0.f, se2 = 0.f;
        #pragma unroll
        for (int j = 0; j < 4; ++j){ e[j] = __expf(lg[j]-m); se += e[j]; se2 += e[j]*e[j]; }
        #pragma unroll
        for (int off = 16; off; off >>= 1){
            se  += __shfl_xor_sync(0xffffffffu, se,  off);
            se2 += __shfl_xor_sync(0xffffffffu, se2, off);
        }
        float inv  = 1.f/se;
        float mu   = (sx + 1.f) * (1.f/(float)DDIM);
        float ef2  = se2*inv*inv*(sxx + 1.f) * (1.f/(float)DDIM);
        float rstd = rsqrtf(ef2 - mu*mu + LN_EPS_C);
        int b = b0 + wg*4 + bi;
        float fr = inv*rstd;
        #pragma unroll
        for (int jp = 0; jp < 2; ++jp){
            int r = 2*lane + 64*jp;
            g_fs[(size_t)b*RU + r + 0] = e[2*jp+0]*fr;
            g_fs[(size_t)b*RU + r + 1] = e[2*jp+1]*fr;
        }
        if (lane == 0) g_c0[b] = -mu*rstd;
    }
}

// ---------------- k2: fused virtual GEMM (packed f32x2 FMA) ----------------
// CTA tile 64b x 64o, 128 threads (each 8b x 4o), split-K over rules (grid.y=NS).
// Per-rule sub-accumulator racc (init = tail weight) folded with fsr once per rule.
__device__ __forceinline__ void ldc_w(float4* pf, int r0, int t, int tid){
    const float* gp = g_WgT + ((size_t)((r0 + (t>>3))*256 + (t&7)*32))*OD + tid*4;
    #pragma unroll
    for (int j = 0; j < 4; ++j) pf[j] = *(const float4*)(gp + j*512);
}

__global__ __launch_bounds__(128,2) void k2_main(const float* __restrict__ X){
    extern __shared__ float sm2[];
    float* Xs = sm2;                // [256][72]  (X transposed: [i][b])
    float* Ws = sm2 + 256*72;       // 2 x [32][64] double-buffered W chunk
    float* Fs = Ws  + 2*2048;       // [16][64]  fsr tile
    float* Wt = Fs  + 1024;         // [16][64]  tail weights
    const int tid = threadIdx.x;
    const int b0  = blockIdx.x * 64;
    const int sp  = blockIdx.y;
    const int r0  = (sp*RU)/NS;
    const int nr  = ((sp+1)*RU)/NS - r0;
    const int og  = tid & 15, bg = tid >> 4;

    for (int q = tid; q < 64*64; q += 128){
        int bb = q >> 6, i4 = (q & 63)*4;
        float4 v = *(const float4*)(X + (size_t)(b0+bb)*IN_D + i4);
        Xs[(i4+0)*72+bb]=v.x; Xs[(i4+1)*72+bb]=v.y;
        Xs[(i4+2)*72+bb]=v.z; Xs[(i4+3)*72+bb]=v.w;
    }
    for (int q = tid; q < nr*64; q += 128){
        int rr = q >> 6, bb = q & 63;
        Fs[q] = g_fs[(size_t)(b0+bb)*RU + r0 + rr];
    }
    for (int q = tid; q < nr*64; q += 128){
        int rr = q >> 6, oo = q & 63;
        Wt[q] = g_WgT[(size_t)(32768 + r0 + rr)*OD + oo];
    }

    float4 pf[4];
    ldc_w(pf, r0, 0, tid);
    #pragma unroll
    for (int j = 0; j < 4; ++j) *(float4*)(Ws + tid*4 + j*512) = pf[j];
    __syncthreads();

    ull acc[4][4], racc[4][4];   // [o_j][b_pair]
    {
        float4 wt = *(const float4*)(Wt + og*4);
        ull w0 = pk2(wt.x), w1 = pk2(wt.y), w2 = pk2(wt.z), w3 = pk2(wt.w);
        #pragma unroll
        for (int p = 0; p < 4; ++p){
            acc[0][p]=0ull; acc[1][p]=0ull; acc[2][p]=0ull; acc[3][p]=0ull;
            racc[0][p]=w0; racc[1][p]=w1; racc[2][p]=w2; racc[3][p]=w3;
        }
    }

    const int total = nr*8;
    int buf = 0;
    for (int t = 0; t < total; ++t){
        if (t+1 < total) ldc_w(pf, r0, t+1, tid);
        if (t && (t & 7) == 0){
            int rp = (t>>3) - 1;
            ulonglong2 f01 = *(const ulonglong2*)(Fs + rp*64 + bg*8);
            ulonglong2 f23 = *(const ulonglong2*)(Fs + rp*64 + bg*8 + 4);
            #pragma unroll
            for (int j = 0; j < 4; ++j){
                fma2(acc[j][0], f01.x, racc[j][0]);
                fma2(acc[j][1], f01.y, racc[j][1]);
                fma2(acc[j][2], f23.x, racc[j][2]);
                fma2(acc[j][3], f23.y, racc[j][3]);
            }
            float4 wt = *(const float4*)(Wt + (t>>3)*64 + og*4);
            ull w0 = pk2(wt.x), w1 = pk2(wt.y), w2 = pk2(wt.z), w3 = pk2(wt.w);
            #pragma unroll
            for (int p = 0; p < 4; ++p){
                racc[0][p]=w0; racc[1][p]=w1; racc[2][p]=w2; racc[3][p]=w3;
            }
        }
        const float* wb   = Ws + buf*2048;
        const float* xrow = Xs + (t & 7)*32*72 + bg*8;
        #pragma unroll 4
        for (int k = 0; k < 32; ++k){
            ulonglong2 A0  = *(const ulonglong2*)(xrow + k*72);
            ulonglong2 A1v = *(const ulonglong2*)(xrow + k*72 + 4);
            float4 w = *(const float4*)(wb + k*64 + og*4);
            ull w0 = pk2(w.x), w1 = pk2(w.y), w2 = pk2(w.z), w3 = pk2(w.w);
            fma2(racc[0][0], A0.x,  w0); fma2(racc[0][1], A0.y,  w0);
            fma2(racc[0][2], A1v.x, w0); fma2(racc[0][3], A1v.y, w0);
            fma2(racc[1][0], A0.x,  w1); fma2(racc[1][1], A0.y,  w1);
            fma2(racc[1][2], A1v.x, w1); fma2(racc[1][3], A1v.y, w1);
            fma2(racc[2][0], A0.x,  w2); fma2(racc[2][1], A0.y,  w2);
            fma2(racc[2][2], A1v.x, w2); fma2(racc[2][3], A1v.y, w2);
            fma2(racc[3][0], A0.x,  w3); fma2(racc[3][1], A0.y,  w3);
            fma2(racc[3][2], A1v.x, w3); fma2(racc[3][3], A1v.y, w3);
        }
        if (t+1 < total){
            #pragma unroll
            for (int j = 0; j < 4; ++j)
                *(float4*)(Ws + (buf^1)*2048 + tid*4 + j*512) = pf[j];
            __syncthreads();
            buf ^= 1;
        }
    }
    {   // fold last rule
        int rp = nr - 1;
        ulonglong2 f01 = *(const ulonglong2*)(Fs + rp*64 + bg*8);
        ulonglong2 f23 = *(const ulonglong2*)(Fs + rp*64 + bg*8 + 4);
        #pragma unroll
        for (int j = 0; j < 4; ++j){
            fma2(acc[j][0], f01.x, racc[j][0]);
            fma2(acc[j][1], f01.y, racc[j][1]);
            fma2(acc[j][2], f23.x, racc[j][2]);
            fma2(acc[j][3], f23.y, racc[j][3]);
        }
    }
    float* outp = g_Part + (size_t)sp*NB*OD;
    #pragma unroll
    for (int p = 0; p < 4; ++p){
        float l0,h0,l1,h1,l2,h2,l3,h3;
        unpk(acc[0][p], l0, h0); unpk(acc[1][p], l1, h1);
        unpk(acc[2][p], l2, h2); unpk(acc[3][p], l3, h3);
        int be = b0 + bg*8 + 2*p;
        *(float4*)(outp + (size_t)be*OD     + og*4) = make_float4(l0,l1,l2,l3);
        *(float4*)(outp + (size_t)(be+1)*OD + og*4) = make_float4(h0,h1,h2,h3);
    }
}

// ---------------- k3: combine partials + affine terms ----------------
__global__ void k3_combine(float* __restrict__ out){
    int idx = blockIdx.x*256 + threadIdx.x;
    if (idx < NB*OD){
        int b = idx >> 6, o = idx & 63;
        float s = g_Bc[o] + g_c0[b]*g_G[o];
        #pragma unroll
        for (int sp = 0; sp < NS; ++sp) s += g_Part[(size_t)sp*NB*OD + idx];
        out[idx] = s;
    }
}

// ---------------- launch ----------------
extern "C" void kernel_launch(void* const* d_in, const int* in_sizes, int n_in,
                              void* d_out, int out_size){
    const float* X       = (const float*)d_in[0];
    const float* centers = (const float*)d_in[1];
    const float* sigmas  = (const float*)d_in[2];
    const float* gamma   = (const float*)d_in[3];
    const float* beta    = (const float*)d_in[4];
    const float* W       = (const float*)d_in[5];
    const float* bias    = (const float*)d_in[6];
    float* out = (float*)d_out;
    (void)in_sizes; (void)n_in; (void)out_size;

    cudaFuncSetAttribute(k1_frs,  cudaFuncAttributeMaxDynamicSharedMemorySize, 50176);
    cudaFuncSetAttribute(k2_main, cudaFuncAttributeMaxDynamicSharedMemorySize, 98304);

    k0_rules<<<(IN_D*RU + 255)/256, 256>>>(centers, sigmas);
    k0_k2c  <<<RU, 64>>>(centers, sigmas);
    k0_wgt  <<<DDIM/64, 256>>>(W, gamma);
    k0_gb   <<<OD, 256>>>(W, gamma, beta, bias);
    k1_frs  <<<NB/16, 128, 50176>>>(X);
    k2_main <<<dim3(NB/64, NS), 128, 98304>>>(X);
    k3_combine<<<(NB*OD + 255)/256, 256>>>(out);
}

// round 3
// speedup vs baseline: 1.0638x; 1.0638x over previous
#include <cuda_runtime.h>

#define IN_D 256
#define RU   128
#define OD   64
#define NB   2048
#define DDIM 32896
#define NS   9
#define HCONST 0.5f
#define EPS_C  1e-8f
#define LN_EPS_C 1e-5f

typedef unsigned long long ull;

// ---------------- device scratch (allocation-free) ----------------
__device__ float g_S  [IN_D*RU];    // H/sigma^2 + eps
__device__ float g_CS [IN_D*RU];    // centers * scale
__device__ float g_K2 [RU];         // sum_i c^2 * scale
__device__ float g_WgT[DDIM*OD];    // gamma[d]*W[o][d], stored [d][o]
__device__ float g_G  [OD];         // sum_d gamma*W      (atomic-accumulated)
__device__ float g_Bc [OD];         // sum_d beta*W       (atomic-accumulated)
__device__ float g_fs [NB*RU];      // frs * rstd
__device__ float g_c0 [NB];         // -mu * rstd
__device__ float g_Part[NS*NB*OD];  // split-K partials

// ---------------- packed f32x2 helpers ----------------
__device__ __forceinline__ ull pk2(float x){
    unsigned u = __float_as_uint(x);
    ull r; asm("mov.b64 %0, {%1, %1};" : "=l"(r) : "r"(u)); return r;
}
__device__ __forceinline__ void fma2(ull &d, ull a, ull b){
    asm("fma.rn.f32x2 %0, %1, %2, %0;" : "+l"(d) : "l"(a), "l"(b));
}
__device__ __forceinline__ void unpk(ull v, float &lo, float &hi){
    unsigned ulo, uhi;
    asm("mov.b64 {%0, %1}, %2;" : "=r"(ulo), "=r"(uhi) : "l"(v));
    lo = __uint_as_float(ulo); hi = __uint_as_float(uhi);
}

// ---------------- k0: rule constants (+ zero G/Bc accumulators) ----------------
__global__ void k0_rules(const float* __restrict__ centers, const float* __restrict__ sigmas){
    int i = blockIdx.x*256 + threadIdx.x;
    if (blockIdx.x == 0){
        if (threadIdx.x < OD)                       g_G [threadIdx.x]      = 0.f;
        else if (threadIdx.x < 2*OD)                g_Bc[threadIdx.x - OD] = 0.f;
    }
    if (i < IN_D*RU){
        float sg = sigmas[i];
        float s  = HCONST/(sg*sg) + EPS_C;
        g_S[i]  = s;
        g_CS[i] = centers[i]*s;
    }
}

__global__ void k0_k2c(const float* __restrict__ centers, const float* __restrict__ sigmas){
    __shared__ float red[64];
    int r = blockIdx.x, tid = threadIdx.x;
    float p = 0.f;
    for (int i = tid; i < IN_D; i += 64){
        float c = centers[i*RU + r], sg = sigmas[i*RU + r];
        float s = HCONST/(sg*sg) + EPS_C;
        p += c*c*s;
    }
    red[tid] = p; __syncthreads();
    for (int s2 = 32; s2 > 0; s2 >>= 1){
        if (tid < s2) red[tid] += red[tid+s2];
        __syncthreads();
    }
    if (tid == 0) g_K2[r] = red[0];
}

// ---------------- k0: WgT = (gamma*W)^T  +  fused G/Bc partial reduction ----------------
// 514 blocks x 256 thr. Tile T[o][f] = W[o][d0+f]. Phase2 writes the transpose;
// the same tile feeds the per-block Sum_f gamma*W / beta*W partials -> atomicAdd.
__global__ void k0_wgt(const float* __restrict__ W, const float* __restrict__ gamma,
                       const float* __restrict__ beta){
    __shared__ float T[64][65];
    __shared__ float ga[64], be[64];
    int tid = threadIdx.x;
    int d0  = blockIdx.x * 64;   // 514 blocks * 64 = 32896
    if (tid < 64){ ga[tid] = gamma[d0 + tid]; be[tid] = beta[d0 + tid]; }
    #pragma unroll
    for (int j = 0; j < 4; ++j){
        int q = tid + j*256;
        int o = q >> 4, f = (q & 15)*4;
        float4 v = *(const float4*)(W + (size_t)o*DDIM + d0 + f);
        T[o][f+0]=v.x; T[o][f+1]=v.y; T[o][f+2]=v.z; T[o][f+3]=v.w;
    }
    __syncthreads();
    #pragma unroll
    for (int j = 0; j < 4; ++j){
        int q = tid + j*256;
        int dd = q >> 4, g4 = (q & 15)*4;
        float gaq = ga[dd];
        float4 ov;
        ov.x = T[g4+0][dd]*gaq; ov.y = T[g4+1][dd]*gaq;
        ov.z = T[g4+2][dd]*gaq; ov.w = T[g4+3][dd]*gaq;
        *(float4*)(g_WgT + (size_t)(d0+dd)*OD + g4) = ov;
    }
    // fused G / Bc partials: thread handles o = tid>>2, f in [seg*16, seg*16+16)
    {
        int o = tid >> 2, seg = tid & 3;
        float sg = 0.f, sb = 0.f;
        #pragma unroll
        for (int u = 0; u < 16; ++u){
            int f = seg*16 + u;
            float w = T[o][f];
            sg += ga[f]*w;
            sb += be[f]*w;
        }
        sg += __shfl_down_sync(0xffffffffu, sg, 2);
        sg += __shfl_down_sync(0xffffffffu, sg, 1);
        sb += __shfl_down_sync(0xffffffffu, sb, 2);
        sb += __shfl_down_sync(0xffffffffu, sb, 1);
        if (seg == 0){
            atomicAdd(&g_G [o], sg);
            atomicAdd(&g_Bc[o], sb);
        }
    }
}

// ---------------- k1: firing levels + softmax + closed-form LN stats ----------------
__global__ __launch_bounds__(128,2) void k1_frs(const float* __restrict__ X){
    extern __shared__ float sm1[];
    float* Xs = sm1;             // [256][17]  (X transposed: [i][b])
    float* Ss = sm1 + 256*17;    // [32][128]
    float* Cs = Ss  + 32*128;    // [32][128]
    __shared__ float K2s[RU];
    const int tid  = threadIdx.x;
    const int b0   = blockIdx.x * 16;
    const int lane = tid & 31, wg = tid >> 5;
    if (tid < RU) K2s[tid] = g_K2[tid];
    for (int q = tid; q < 16*64; q += 128){
        int bb = q >> 6, i4 = (q & 63)*4;
        float4 v = *(const float4*)(X + (size_t)(b0+bb)*IN_D + i4);
        Xs[(i4+0)*17+bb]=v.x; Xs[(i4+1)*17+bb]=v.y;
        Xs[(i4+2)*17+bb]=v.z; Xs[(i4+3)*17+bb]=v.w;
    }
    ull A1p[4][2], A2p[4][2];
    #pragma unroll
    for (int bi = 0; bi < 4; ++bi){
        A1p[bi][0]=0ull; A1p[bi][1]=0ull; A2p[bi][0]=0ull; A2p[bi][1]=0ull;
    }
    for (int c = 0; c < 8; ++c){
        __syncthreads();
        for (int q = tid; q < 32*32; q += 128){
            int row = q >> 5, col4 = (q & 31)*4;
            *(float4*)(Ss + row*RU + col4) = *(const float4*)(g_S  + (size_t)(c*32+row)*RU + col4);
            *(float4*)(Cs + row*RU + col4) = *(const float4*)(g_CS + (size_t)(c*32+row)*RU + col4);
        }
        __syncthreads();
        #pragma unroll 4
        for (int k = 0; k < 32; ++k){
            int i = c*32 + k;
            float x0 = Xs[i*17 + wg*4 + 0];
            float x1 = Xs[i*17 + wg*4 + 1];
            float x2 = Xs[i*17 + wg*4 + 2];
            float x3 = Xs[i*17 + wg*4 + 3];
            ull xx0 = pk2(x0*x0), xx1 = pk2(x1*x1), xx2 = pk2(x2*x2), xx3 = pk2(x3*x3);
            ull xp0 = pk2(x0),    xp1 = pk2(x1),    xp2 = pk2(x2),    xp3 = pk2(x3);
            #pragma unroll
            for (int jp = 0; jp < 2; ++jp){
                ull s2 = *(const ull*)(Ss + k*RU + 2*lane + 64*jp);
                ull c2 = *(const ull*)(Cs + k*RU + 2*lane + 64*jp);
                fma2(A1p[0][jp], xx0, s2); fma2(A1p[1][jp], xx1, s2);
                fma2(A1p[2][jp], xx2, s2); fma2(A1p[3][jp], xx3, s2);
                fma2(A2p[0][jp], xp0, c2); fma2(A2p[1][jp], xp1, c2);
                fma2(A2p[2][jp], xp2, c2); fma2(A2p[3][jp], xp3, c2);
            }
        }
    }
    #pragma unroll
    for (int bi = 0; bi < 4; ++bi){
        float sx = 0.f, sxx = 0.f;
        #pragma unroll
        for (int t = 0; t < 8; ++t){
            float x = Xs[(lane + 32*t)*17 + wg*4 + bi];
            sx += x; sxx += x*x;
        }
        #pragma unroll
        for (int off = 16; off; off >>= 1){
            sx  += __shfl_xor_sync(0xffffffffu, sx,  off);
            sxx += __shfl_xor_sync(0xffffffffu, sxx, off);
        }
        float lg[4], e[4];
        #pragma unroll
        for (int jp = 0; jp < 2; ++jp){
            float a1l,a1h,a2l,a2h;
            unpk(A1p[bi][jp], a1l, a1h);
            unpk(A2p[bi][jp], a2l, a2h);
            int r = 2*lane + 64*jp;
            lg[2*jp+0] = -(a1l - 2.f*a2l + K2s[r+0]) * (1.f/256.f);
            lg[2*jp+1] = -(a1h - 2.f*a2h + K2s[r+1]) * (1.f/256.f);
        }
        float m = fmaxf(fmaxf(lg[0],lg[1]), fmaxf(lg[2],lg[3]));
        #pragma unroll
        for (int off = 16; off; off >>= 1)
            m = fmaxf(m, __shfl_xor_sync(0xffffffffu, m, off));
        float se = 0.f, se2 = 0.f;
        #pragma unroll
        for (int j = 0; j < 4; ++j){ e[j] = __expf(lg[j]-m); se += e[j]; se2 += e[j]*e[j]; }
        #pragma unroll
        for (int off = 16; off; off >>= 1){
            se  += __shfl_xor_sync(0xffffffffu, se,  off);
            se2 += __shfl_xor_sync(0xffffffffu, se2, off);
        }
        float inv  = 1.f/se;
        float mu   = (sx + 1.f) * (1.f/(float)DDIM);
        float ef2  = se2*inv*inv*(sxx + 1.f) * (1.f/(float)DDIM);
        float rstd = rsqrtf(ef2 - mu*mu + LN_EPS_C);
        int b = b0 + wg*4 + bi;
        float fr = inv*rstd;
        #pragma unroll
        for (int jp = 0; jp < 2; ++jp){
            int r = 2*lane + 64*jp;
            g_fs[(size_t)b*RU + r + 0] = e[2*jp+0]*fr;
            g_fs[(size_t)b*RU + r + 1] = e[2*jp+1]*fr;
        }
        if (lane == 0) g_c0[b] = -mu*rstd;
    }
}

// ---------------- k2: fused virtual GEMM (packed f32x2 FMA) ----------------
__device__ __forceinline__ void ldc_w(float4* pf, int r0, int t, int tid){
    const float* gp = g_WgT + ((size_t)((r0 + (t>>3))*256 + (t&7)*32))*OD + tid*4;
    #pragma unroll
    for (int j = 0; j < 4; ++j) pf[j] = *(const float4*)(gp + j*512);
}

__global__ __launch_bounds__(128,2) void k2_main(const float* __restrict__ X){
    extern __shared__ float sm2[];
    float* Xs = sm2;                // [256][72]  (X transposed: [i][b])
    float* Ws = sm2 + 256*72;       // 2 x [32][64] double-buffered W chunk
    float* Fs = Ws  + 2*2048;       // [16][64]  fsr tile
    float* Wt = Fs  + 1024;         // [16][64]  tail weights
    const int tid = threadIdx.x;
    const int b0  = blockIdx.x * 64;
    const int sp  = blockIdx.y;
    const int r0  = (sp*RU)/NS;
    const int nr  = ((sp+1)*RU)/NS - r0;
    const int og  = tid & 15, bg = tid >> 4;

    for (int q = tid; q < 64*64; q += 128){
        int bb = q >> 6, i4 = (q & 63)*4;
        float4 v = *(const float4*)(X + (size_t)(b0+bb)*IN_D + i4);
        Xs[(i4+0)*72+bb]=v.x; Xs[(i4+1)*72+bb]=v.y;
        Xs[(i4+2)*72+bb]=v.z; Xs[(i4+3)*72+bb]=v.w;
    }
    for (int q = tid; q < nr*64; q += 128){
        int rr = q >> 6, bb = q & 63;
        Fs[q] = g_fs[(size_t)(b0+bb)*RU + r0 + rr];
    }
    for (int q = tid; q < nr*64; q += 128){
        int rr = q >> 6, oo = q & 63;
        Wt[q] = g_WgT[(size_t)(32768 + r0 + rr)*OD + oo];
    }

    float4 pf[4];
    ldc_w(pf, r0, 0, tid);
    #pragma unroll
    for (int j = 0; j < 4; ++j) *(float4*)(Ws + tid*4 + j*512) = pf[j];
    __syncthreads();

    ull acc[4][4], racc[4][4];   // [o_j][b_pair]
    {
        float4 wt = *(const float4*)(Wt + og*4);
        ull w0 = pk2(wt.x), w1 = pk2(wt.y), w2 = pk2(wt.z), w3 = pk2(wt.w);
        #pragma unroll
        for (int p = 0; p < 4; ++p){
            acc[0][p]=0ull; acc[1][p]=0ull; acc[2][p]=0ull; acc[3][p]=0ull;
            racc[0][p]=w0; racc[1][p]=w1; racc[2][p]=w2; racc[3][p]=w3;
        }
    }

    const int total = nr*8;
    int buf = 0;
    for (int t = 0; t < total; ++t){
        if (t+1 < total) ldc_w(pf, r0, t+1, tid);
        if (t && (t & 7) == 0){
            int rp = (t>>3) - 1;
            ulonglong2 f01 = *(const ulonglong2*)(Fs + rp*64 + bg*8);
            ulonglong2 f23 = *(const ulonglong2*)(Fs + rp*64 + bg*8 + 4);
            #pragma unroll
            for (int j = 0; j < 4; ++j){
                fma2(acc[j][0], f01.x, racc[j][0]);
                fma2(acc[j][1], f01.y, racc[j][1]);
                fma2(acc[j][2], f23.x, racc[j][2]);
                fma2(acc[j][3], f23.y, racc[j][3]);
            }
            float4 wt = *(const float4*)(Wt + (t>>3)*64 + og*4);
            ull w0 = pk2(wt.x), w1 = pk2(wt.y), w2 = pk2(wt.z), w3 = pk2(wt.w);
            #pragma unroll
            for (int p = 0; p < 4; ++p){
                racc[0][p]=w0; racc[1][p]=w1; racc[2][p]=w2; racc[3][p]=w3;
            }
        }
        const float* wb   = Ws + buf*2048;
        const float* xrow = Xs + (t & 7)*32*72 + bg*8;
        #pragma unroll 4
        for (int k = 0; k < 32; ++k){
            ulonglong2 A0  = *(const ulonglong2*)(xrow + k*72);
            ulonglong2 A1v = *(const ulonglong2*)(xrow + k*72 + 4);
            float4 w = *(const float4*)(wb + k*64 + og*4);
            ull w0 = pk2(w.x), w1 = pk2(w.y), w2 = pk2(w.z), w3 = pk2(w.w);
            fma2(racc[0][0], A0.x,  w0); fma2(racc[0][1], A0.y,  w0);
            fma2(racc[0][2], A1v.x, w0); fma2(racc[0][3], A1v.y, w0);
            fma2(racc[1][0], A0.x,  w1); fma2(racc[1][1], A0.y,  w1);
            fma2(racc[1][2], A1v.x, w1); fma2(racc[1][3], A1v.y, w1);
            fma2(racc[2][0], A0.x,  w2); fma2(racc[2][1], A0.y,  w2);
            fma2(racc[2][2], A1v.x, w2); fma2(racc[2][3], A1v.y, w2);
            fma2(racc[3][0], A0.x,  w3); fma2(racc[3][1], A0.y,  w3);
            fma2(racc[3][2], A1v.x, w3); fma2(racc[3][3], A1v.y, w3);
        }
        if (t+1 < total){
            #pragma unroll
            for (int j = 0; j < 4; ++j)
                *(float4*)(Ws + (buf^1)*2048 + tid*4 + j*512) = pf[j];
            __syncthreads();
            buf ^= 1;
        }
    }
    {   // fold last rule
        int rp = nr - 1;
        ulonglong2 f01 = *(const ulonglong2*)(Fs + rp*64 + bg*8);
        ulonglong2 f23 = *(const ulonglong2*)(Fs + rp*64 + bg*8 + 4);
        #pragma unroll
        for (int j = 0; j < 4; ++j){
            fma2(acc[j][0], f01.x, racc[j][0]);
            fma2(acc[j][1], f01.y, racc[j][1]);
            fma2(acc[j][2], f23.x, racc[j][2]);
            fma2(acc[j][3], f23.y, racc[j][3]);
        }
    }
    float* outp = g_Part + (size_t)sp*NB*OD;
    #pragma unroll
    for (int p = 0; p < 4; ++p){
        float l0,h0,l1,h1,l2,h2,l3,h3;
        unpk(acc[0][p], l0, h0); unpk(acc[1][p], l1, h1);
        unpk(acc[2][p], l2, h2); unpk(acc[3][p], l3, h3);
        int be = b0 + bg*8 + 2*p;
        *(float4*)(outp + (size_t)be*OD     + og*4) = make_float4(l0,l1,l2,l3);
        *(float4*)(outp + (size_t)(be+1)*OD + og*4) = make_float4(h0,h1,h2,h3);
    }
}

// ---------------- k3: combine partials + affine terms (+bias) ----------------
__global__ void k3_combine(float* __restrict__ out, const float* __restrict__ bias){
    int idx = blockIdx.x*256 + threadIdx.x;
    if (idx < NB*OD){
        int b = idx >> 6, o = idx & 63;
        float s = g_Bc[o] + bias[o] + g_c0[b]*g_G[o];
        #pragma unroll
        for (int sp = 0; sp < NS; ++sp) s += g_Part[(size_t)sp*NB*OD + idx];
        out[idx] = s;
    }
}

// ---------------- launch ----------------
extern "C" void kernel_launch(void* const* d_in, const int* in_sizes, int n_in,
                              void* d_out, int out_size){
    const float* X       = (const float*)d_in[0];
    const float* centers = (const float*)d_in[1];
    const float* sigmas  = (const float*)d_in[2];
    const float* gamma   = (const float*)d_in[3];
    const float* beta    = (const float*)d_in[4];
    const float* W       = (const float*)d_in[5];
    const float* bias    = (const float*)d_in[6];
    float* out = (float*)d_out;
    (void)in_sizes; (void)n_in; (void)out_size;

    cudaFuncSetAttribute(k1_frs,  cudaFuncAttributeMaxDynamicSharedMemorySize, 50176);
    cudaFuncSetAttribute(k2_main, cudaFuncAttributeMaxDynamicSharedMemorySize, 98304);

    k0_rules<<<(IN_D*RU + 255)/256, 256>>>(centers, sigmas);
    k0_k2c  <<<RU, 64>>>(centers, sigmas);
    k0_wgt  <<<DDIM/64, 256>>>(W, gamma, beta);
    k1_frs  <<<NB/16, 128, 50176>>>(X);
    k2_main <<<dim3(NB/64, NS), 128, 98304>>>(X);
    k3_combine<<<(NB*OD + 255)/256, 256>>>(out, bias);
}

// round 5
// speedup vs baseline: 1.5553x; 1.4620x over previous
#include <cuda_runtime.h>
#include <cuda_bf16.h>
#include <mma.h>

using namespace nvcuda;

#define IN_D 256
#define RU   128
#define OD   64
#define NB   2048
#define DDIM 32896
#define HCONST 0.5f
#define EPS_C  1e-8f
#define LN_EPS_C 1e-5f

typedef unsigned long long ull;

// ---------------- device scratch (allocation-free) ----------------
__device__ float    g_S  [IN_D*RU];
__device__ float    g_CS [IN_D*RU];
__device__ float    g_K2 [RU];
__device__ float    g_G  [OD];
__device__ float    g_Bc [OD];
__device__ float    g_fsT[RU*NB];      // (frs*rstd) TRANSPOSED: [r][b]
__device__ float    g_c0 [NB];         // -mu*rstd
__device__ float    g_Wt [OD*RU];      // tail weights gamma*W[o][32768+r]
__device__ unsigned g_Bhi[256*4096];   // B hi split  [i=256][8192 n] bf16x2 words, n=o*128+r
__device__ unsigned g_Blo[256*4096];
__device__ unsigned g_Xhi[NB*128];     // X hi split  [b][256 i] bf16x2 words
__device__ unsigned g_Xlo[NB*128];

// ---------------- helpers ----------------
__device__ __forceinline__ ull pk2(float x){
    unsigned u = __float_as_uint(x);
    ull r; asm("mov.b64 %0, {%1, %1};" : "=l"(r) : "r"(u)); return r;
}
__device__ __forceinline__ void fma2(ull &d, ull a, ull b){
    asm("fma.rn.f32x2 %0, %1, %2, %0;" : "+l"(d) : "l"(a), "l"(b));
}
__device__ __forceinline__ void unpk(ull v, float &lo, float &hi){
    unsigned ulo, uhi;
    asm("mov.b64 {%0, %1}, %2;" : "=r"(ulo), "=r"(uhi) : "l"(v));
    lo = __uint_as_float(ulo); hi = __uint_as_float(uhi);
}
// bf16 2-term split of (a,b): hi = {bf16(b),bf16(a)}, lo = bf16 residuals
__device__ __forceinline__ void split_pack(float a, float b, unsigned &hi, unsigned &lo){
    unsigned h; asm("cvt.rn.bf16x2.f32 %0, %1, %2;" : "=r"(h) : "f"(b), "f"(a));
    float ra = __uint_as_float(h << 16);
    float rb = __uint_as_float(h & 0xFFFF0000u);
    float la = a - ra, lb = b - rb;
    unsigned l; asm("cvt.rn.bf16x2.f32 %0, %1, %2;" : "=r"(l) : "f"(lb), "f"(la));
    hi = h; lo = l;
}

// ---------------- k0: rule constants (+ zero G/Bc) ----------------
__global__ void k0_rules(const float* __restrict__ centers, const float* __restrict__ sigmas){
    int i = blockIdx.x*256 + threadIdx.x;
    if (blockIdx.x == 0){
        if (threadIdx.x < OD)          g_G [threadIdx.x]      = 0.f;
        else if (threadIdx.x < 2*OD)   g_Bc[threadIdx.x - OD] = 0.f;
    }
    if (i < IN_D*RU){
        float sg = sigmas[i];
        float s  = HCONST/(sg*sg) + EPS_C;
        g_S[i]  = s;
        g_CS[i] = centers[i]*s;
    }
}

__global__ void k0_k2c(const float* __restrict__ centers, const float* __restrict__ sigmas){
    __shared__ float red[64];
    int r = blockIdx.x, tid = threadIdx.x;
    float p = 0.f;
    for (int i = tid; i < IN_D; i += 64){
        float c = centers[i*RU + r], sg = sigmas[i*RU + r];
        float s = HCONST/(sg*sg) + EPS_C;
        p += c*c*s;
    }
    red[tid] = p; __syncthreads();
    for (int s2 = 32; s2 > 0; s2 >>= 1){
        if (tid < s2) red[tid] += red[tid+s2];
        __syncthreads();
    }
    if (tid == 0) g_K2[r] = red[0];
}

// ---------------- k0: X -> bf16 hi/lo split ----------------
__global__ void k0_xsplit(const float* __restrict__ X){
    int p = blockIdx.x*256 + threadIdx.x;   // pair index, 2048*128 total
    if (p < NB*128){
        float2 x = *(const float2*)(X + 2*(size_t)p);
        unsigned hi, lo; split_pack(x.x, x.y, hi, lo);
        g_Xhi[p] = hi; g_Xlo[p] = lo;
    }
}

// ---------------- k0: B = gamma*W rearranged [i][(o*128+r)] bf16 hi/lo + Wt + G/Bc ----------------
// grid (8 rc, 64 o), 256 thr. Thread t owns i=t; reads (r, i=t) for 16 r's (coalesced rows),
// keeps vals in registers (no transpose needed), writes 16 contiguous n-cols (32B) per array.
__global__ void k0_bsplit(const float* __restrict__ W, const float* __restrict__ gamma,
                          const float* __restrict__ beta){
    __shared__ float rg[8], rb[8];
    int rc = blockIdx.x, o = blockIdx.y;
    int t = threadIdx.x, lane = t & 31, w = t >> 5;
    float vals[16];
    float sg = 0.f, sb = 0.f;
    #pragma unroll
    for (int rr = 0; rr < 16; ++rr){
        int d = (rc*16 + rr)*256 + t;
        float wv = W[(size_t)o*DDIM + d];
        float gv = gamma[d]*wv;
        vals[rr] = gv;
        sg += gv; sb += beta[d]*wv;
    }
    if (rc == 0 && t < 128){
        int d = 32768 + t;
        float wv = W[(size_t)o*DDIM + d];
        float gv = gamma[d]*wv;
        g_Wt[o*RU + t] = gv;
        sg += gv; sb += beta[d]*wv;
    }
    {
        unsigned* bh = g_Bhi + (size_t)t*4096 + o*64 + rc*8;
        unsigned* bl = g_Blo + (size_t)t*4096 + o*64 + rc*8;
        #pragma unroll
        for (int p = 0; p < 8; ++p){
            unsigned hi, lo; split_pack(vals[2*p], vals[2*p+1], hi, lo);
            bh[p] = hi; bl[p] = lo;
        }
    }
    #pragma unroll
    for (int off = 16; off; off >>= 1){
        sg += __shfl_down_sync(0xffffffffu, sg, off);
        sb += __shfl_down_sync(0xffffffffu, sb, off);
    }
    if (lane == 0){ rg[w] = sg; rb[w] = sb; }
    __syncthreads();
    if (t == 0){
        float a = 0.f, b2 = 0.f;
        #pragma unroll
        for (int u = 0; u < 8; ++u){ a += rg[u]; b2 += rb[u]; }
        atomicAdd(&g_G[o], a); atomicAdd(&g_Bc[o], b2);
    }
}

// ---------------- k1: firing levels + softmax + closed-form LN stats ----------------
// 128 thr, 8 batch rows/CTA, 256 CTAs, 4 CTAs/SM target. Writes fsr TRANSPOSED.
__global__ __launch_bounds__(128,4) void k1_frs(const float* __restrict__ X){
    extern __shared__ float sm1[];
    float* Xs = sm1;             // [256][9]
    float* Ss = sm1 + 256*9;     // [32][128]
    float* Cs = Ss  + 32*128;    // [32][128]
    __shared__ float K2s[RU];
    const int tid  = threadIdx.x;
    const int b0   = blockIdx.x * 8;
    const int lane = tid & 31, wg = tid >> 5;
    if (tid < RU) K2s[tid] = g_K2[tid];
    for (int q = tid; q < 8*64; q += 128){
        int bb = q >> 6, i4 = (q & 63)*4;
        float4 v = *(const float4*)(X + (size_t)(b0+bb)*IN_D + i4);
        Xs[(i4+0)*9+bb]=v.x; Xs[(i4+1)*9+bb]=v.y;
        Xs[(i4+2)*9+bb]=v.z; Xs[(i4+3)*9+bb]=v.w;
    }
    ull A1p[2][2], A2p[2][2];
    #pragma unroll
    for (int bi = 0; bi < 2; ++bi){
        A1p[bi][0]=0ull; A1p[bi][1]=0ull; A2p[bi][0]=0ull; A2p[bi][1]=0ull;
    }
    for (int c = 0; c < 8; ++c){
        __syncthreads();
        for (int q = tid; q < 32*32; q += 128){
            int row = q >> 5, col4 = (q & 31)*4;
            *(float4*)(Ss + row*RU + col4) = *(const float4*)(g_S  + (size_t)(c*32+row)*RU + col4);
            *(float4*)(Cs + row*RU + col4) = *(const float4*)(g_CS + (size_t)(c*32+row)*RU + col4);
        }
        __syncthreads();
        #pragma unroll 4
        for (int k = 0; k < 32; ++k){
            int i = c*32 + k;
            float x0 = Xs[i*9 + wg*2 + 0];
            float x1 = Xs[i*9 + wg*2 + 1];
            ull xx0 = pk2(x0*x0), xx1 = pk2(x1*x1);
            ull xp0 = pk2(x0),    xp1 = pk2(x1);
            #pragma unroll
            for (int jp = 0; jp < 2; ++jp){
                ull s2 = *(const ull*)(Ss + k*RU + 2*lane + 64*jp);
                ull c2 = *(const ull*)(Cs + k*RU + 2*lane + 64*jp);
                fma2(A1p[0][jp], xx0, s2); fma2(A1p[1][jp], xx1, s2);
                fma2(A2p[0][jp], xp0, c2); fma2(A2p[1][jp], xp1, c2);
            }
        }
    }
    #pragma unroll
    for (int bi = 0; bi < 2; ++bi){
        float sx = 0.f, sxx = 0.f;
        #pragma unroll
        for (int t = 0; t < 8; ++t){
            float x = Xs[(lane + 32*t)*9 + wg*2 + bi];
            sx += x; sxx += x*x;
        }
        #pragma unroll
        for (int off = 16; off; off >>= 1){
            sx  += __shfl_xor_sync(0xffffffffu, sx,  off);
            sxx += __shfl_xor_sync(0xffffffffu, sxx, off);
        }
        float lg[4], e[4];
        #pragma unroll
        for (int jp = 0; jp < 2; ++jp){
            float a1l,a1h,a2l,a2h;
            unpk(A1p[bi][jp], a1l, a1h);
            unpk(A2p[bi][jp], a2l, a2h);
            int r = 2*lane + 64*jp;
            lg[2*jp+0] = -(a1l - 2.f*a2l + K2s[r+0]) * (1.f/256.f);
            lg[2*jp+1] = -(a1h - 2.f*a2h + K2s[r+1]) * (1.f/256.f);
        }
        float m = fmaxf(fmaxf(lg[0],lg[1]), fmaxf(lg[2],lg[3]));
        #pragma unroll
        for (int off = 16; off; off >>= 1)
            m = fmaxf(m, __shfl_xor_sync(0xffffffffu, m, off));
        float se = 0.f, se2 = 0.f;
        #pragma unroll
        for (int j = 0; j < 4; ++j){ e[j] = __expf(lg[j]-m); se += e[j]; se2 += e[j]*e[j]; }
        #pragma unroll
        for (int off = 16; off; off >>= 1){
            se  += __shfl_xor_sync(0xffffffffu, se,  off);
            se2 += __shfl_xor_sync(0xffffffffu, se2, off);
        }
        float inv  = 1.f/se;
        float mu   = (sx + 1.f) * (1.f/(float)DDIM);
        float ef2  = se2*inv*inv*(sxx + 1.f) * (1.f/(float)DDIM);
        float rstd = rsqrtf(ef2 - mu*mu + LN_EPS_C);
        int b = b0 + wg*2 + bi;
        float fr = inv*rstd;
        #pragma unroll
        for (int jp = 0; jp < 2; ++jp){
            int r = 2*lane + 64*jp;
            g_fsT[(size_t)(r  )*NB + b] = e[2*jp+0]*fr;
            g_fsT[(size_t)(r+1)*NB + b] = e[2*jp+1]*fr;
        }
        if (lane == 0) g_c0[b] = -mu*rstd;
    }
}

// ---------------- k2: bf16 wmma GEMM (3-pass split) + fused rule-reduction epilogue ----------------
// Grid (16 b-tiles, 64 o). CTA 256 thr = 8 warps (4m x 2n). Tile M=128 (batch), N=128 (=rules of o), K=256.
#define A_LD 72
#define B_LD 136
#define OFF_AH 0u
#define OFF_AL 18432u
#define OFF_BH 36864u
#define OFF_BL 54272u
#define OFF_WT 71680u
#define K2_SMEM 72192u

__global__ __launch_bounds__(256,2) void k2_wmma(const float* __restrict__ bias,
                                                 float* __restrict__ out){
    extern __shared__ __align__(16) char sm[];
    __nv_bfloat16* Ah = (__nv_bfloat16*)(sm + OFF_AH);
    __nv_bfloat16* Al = (__nv_bfloat16*)(sm + OFF_AL);
    __nv_bfloat16* Bh = (__nv_bfloat16*)(sm + OFF_BH);
    __nv_bfloat16* Bl = (__nv_bfloat16*)(sm + OFF_BL);
    float* Wts = (float*)(sm + OFF_WT);
    float* Ps  = (float*)sm;                 // epilogue overlay [b + r*132]
    const int tid = threadIdx.x;
    const int b0  = blockIdx.x * 128;
    const int o   = blockIdx.y;
    const int w   = tid >> 5;
    const int mw  = w >> 1, nw = w & 1;

    if (tid < 128) Wts[tid] = g_Wt[o*RU + tid];

    wmma::fragment<wmma::accumulator,16,16,16,float> acc[2][4];
    #pragma unroll
    for (int mt = 0; mt < 2; ++mt)
        #pragma unroll
        for (int nt = 0; nt < 4; ++nt) wmma::fill_fragment(acc[mt][nt], 0.f);

    for (int kc = 0; kc < 4; ++kc){
        __syncthreads();
        // A chunk: [128 b][64 k] bf16 hi/lo, row pitch A_LD els (144B) -> uint2 copies
        for (int q = tid; q < 2048; q += 256){
            int row = q >> 4, s = q & 15;
            const uint2* srcH = (const uint2*)(g_Xhi + (size_t)(b0+row)*128 + kc*32) + s;
            const uint2* srcL = (const uint2*)(g_Xlo + (size_t)(b0+row)*128 + kc*32) + s;
            *(uint2*)(sm + OFF_AH + row*144 + s*8) = *srcH;
            *(uint2*)(sm + OFF_AL + row*144 + s*8) = *srcL;
        }
        // B chunk: [64 k][128 n] bf16 hi/lo, row pitch B_LD els (272B) -> uint4 copies
        for (int q = tid; q < 1024; q += 256){
            int k = q >> 4, s = q & 15;
            const uint4* srcH = (const uint4*)(g_Bhi + (size_t)(kc*64+k)*4096 + o*64) + s;
            const uint4* srcL = (const uint4*)(g_Blo + (size_t)(kc*64+k)*4096 + o*64) + s;
            *(uint4*)(sm + OFF_BH + k*272 + s*16) = *srcH;
            *(uint4*)(sm + OFF_BL + k*272 + s*16) = *srcL;
        }
        __syncthreads();
        #pragma unroll
        for (int ks = 0; ks < 4; ++ks){
            wmma::fragment<wmma::matrix_a,16,16,16,__nv_bfloat16,wmma::row_major> ah[2], al[2];
            #pragma unroll
            for (int mt = 0; mt < 2; ++mt){
                const __nv_bfloat16* ap = Ah + (mw*32 + mt*16)*A_LD + ks*16;
                const __nv_bfloat16* lp = Al + (mw*32 + mt*16)*A_LD + ks*16;
                wmma::load_matrix_sync(ah[mt], ap, A_LD);
                wmma::load_matrix_sync(al[mt], lp, A_LD);
            }
            #pragma unroll
            for (int nt = 0; nt < 4; ++nt){
                wmma::fragment<wmma::matrix_b,16,16,16,__nv_bfloat16,wmma::row_major> bh, bl;
                wmma::load_matrix_sync(bh, Bh + ks*16*B_LD + nw*64 + nt*16, B_LD);
                wmma::load_matrix_sync(bl, Bl + ks*16*B_LD + nw*64 + nt*16, B_LD);
                #pragma unroll
                for (int mt = 0; mt < 2; ++mt){
                    wmma::mma_sync(acc[mt][nt], ah[mt], bh, acc[mt][nt]);
                    wmma::mma_sync(acc[mt][nt], ah[mt], bl, acc[mt][nt]);
                    wmma::mma_sync(acc[mt][nt], al[mt], bh, acc[mt][nt]);
                }
            }
        }
    }
    __syncthreads();
    // stage P col-major: element (b_local, r) at Ps[b + r*132]
    #pragma unroll
    for (int mt = 0; mt < 2; ++mt)
        #pragma unroll
        for (int nt = 0; nt < 4; ++nt)
            wmma::store_matrix_sync(Ps + (mw*32 + mt*16) + (size_t)(nw*64 + nt*16)*132,
                                    acc[mt][nt], 132, wmma::mem_col_major);
    __syncthreads();
    if (tid < 128){
        int b = b0 + tid;
        float s = 0.f;
        #pragma unroll 4
        for (int r = 0; r < 128; ++r)
            s += g_fsT[(size_t)r*NB + b] * (Ps[tid + r*132] + Wts[r]);
        out[(size_t)b*OD + o] = s + g_c0[b]*g_G[o] + g_Bc[o] + bias[o];
    }
}

// ---------------- launch ----------------
extern "C" void kernel_launch(void* const* d_in, const int* in_sizes, int n_in,
                              void* d_out, int out_size){
    const float* X       = (const float*)d_in[0];
    const float* centers = (const float*)d_in[1];
    const float* sigmas  = (const float*)d_in[2];
    const float* gamma   = (const float*)d_in[3];
    const float* beta    = (const float*)d_in[4];
    const float* W       = (const float*)d_in[5];
    const float* bias    = (const float*)d_in[6];
    float* out = (float*)d_out;
    (void)in_sizes; (void)n_in; (void)out_size;

    cudaFuncSetAttribute(k1_frs,  cudaFuncAttributeMaxDynamicSharedMemorySize, 42112);
    cudaFuncSetAttribute(k2_wmma, cudaFuncAttributeMaxDynamicSharedMemorySize, K2_SMEM);

    k0_rules <<<(IN_D*RU + 255)/256, 256>>>(centers, sigmas);
    k0_k2c   <<<RU, 64>>>(centers, sigmas);
    k0_xsplit<<<(NB*128 + 255)/256, 256>>>(X);
    k0_bsplit<<<dim3(8, 64), 256>>>(W, gamma, beta);
    k1_frs   <<<NB/8, 128, 42112>>>(X);
    k2_wmma  <<<dim3(NB/128, OD), 256, K2_SMEM>>>(bias, out);
}

// round 6
// speedup vs baseline: 1.7949x; 1.1541x over previous
#include <cuda_runtime.h>
#include <cuda_bf16.h>
#include <mma.h>

using namespace nvcuda;

#define IN_D 256
#define RU   128
#define OD   64
#define NB   2048
#define DDIM 32896
#define HCONST 0.5f
#define EPS_C  1e-8f
#define LN_EPS_C 1e-5f

typedef unsigned long long ull;

// ---------------- device scratch (allocation-free) ----------------
__device__ float    g_S  [IN_D*RU];
__device__ float    g_CS [IN_D*RU];
__device__ float    g_K2 [RU];
__device__ float    g_G  [OD];
__device__ float    g_Bc [OD];
__device__ float    g_fsT[RU*NB];      // (frs*rstd) transposed: [r][b]
__device__ float    g_c0 [NB];         // -mu*rstd
__device__ float    g_Wt [OD*RU];      // tail weights gamma*W[o][32768+r]
__device__ unsigned g_Bhi[256*4096];   // B hi split [i=256][n_w=4096] bf16x2, n_w = o*64 + r/2
__device__ unsigned g_Blo[256*4096];
__device__ unsigned g_Xhi[NB*128];     // X hi split [b][128 words]
__device__ unsigned g_Xlo[NB*128];

// ---------------- helpers ----------------
__device__ __forceinline__ ull pk2(float x){
    unsigned u = __float_as_uint(x);
    ull r; asm("mov.b64 %0, {%1, %1};" : "=l"(r) : "r"(u)); return r;
}
__device__ __forceinline__ void fma2(ull &d, ull a, ull b){
    asm("fma.rn.f32x2 %0, %1, %2, %0;" : "+l"(d) : "l"(a), "l"(b));
}
__device__ __forceinline__ void unpk(ull v, float &lo, float &hi){
    unsigned ulo, uhi;
    asm("mov.b64 {%0, %1}, %2;" : "=r"(ulo), "=r"(uhi) : "l"(v));
    lo = __uint_as_float(ulo); hi = __uint_as_float(uhi);
}
// bf16 2-term split of (a,b): hi = {bf16(b),bf16(a)}, lo = bf16 residuals
__device__ __forceinline__ void split_pack(float a, float b, unsigned &hi, unsigned &lo){
    unsigned h; asm("cvt.rn.bf16x2.f32 %0, %1, %2;" : "=r"(h) : "f"(b), "f"(a));
    float ra = __uint_as_float(h << 16);
    float rb = __uint_as_float(h & 0xFFFF0000u);
    float la = a - ra, lb = b - rb;
    unsigned l; asm("cvt.rn.bf16x2.f32 %0, %1, %2;" : "=r"(l) : "f"(lb), "f"(la));
    hi = h; lo = l;
}
__device__ __forceinline__ unsigned smem_u32(const void* p){
    unsigned a;
    asm("{ .reg .u64 t; cvta.to.shared.u64 t, %1; cvt.u32.u64 %0, t; }" : "=r"(a) : "l"(p));
    return a;
}
__device__ __forceinline__ void cpa16(unsigned dst, const void* src){
    asm volatile("cp.async.cg.shared.global [%0], [%1], 16;" :: "r"(dst), "l"(src) : "memory");
}
#define CPA_COMMIT() asm volatile("cp.async.commit_group;" ::: "memory")
#define CPA_WAIT1()  asm volatile("cp.async.wait_group 1;" ::: "memory")
#define CPA_WAIT0()  asm volatile("cp.async.wait_group 0;" ::: "memory")

// ---------------- k0a: rule constants + X split (+ zero G/Bc) ----------------
__global__ void k0a_prep(const float* __restrict__ centers, const float* __restrict__ sigmas,
                         const float* __restrict__ X){
    int t = threadIdx.x, blk = blockIdx.x;
    int p = blk*256 + t;                 // 1024 blocks cover X pairs
    if (p < NB*128){
        float2 x = *(const float2*)(X + 2*(size_t)p);
        unsigned hi, lo; split_pack(x.x, x.y, hi, lo);
        g_Xhi[p] = hi; g_Xlo[p] = lo;
    }
    if (blk < 128){
        int i = blk*256 + t;
        float sg = sigmas[i];
        float s  = HCONST/(sg*sg) + EPS_C;
        g_S[i]  = s;
        g_CS[i] = centers[i]*s;
    }
    if (blk == 0){
        if (t < OD)          g_G [t]      = 0.f;
        else if (t < 2*OD)   g_Bc[t - OD] = 0.f;
    }
}

__global__ void k0_k2c(const float* __restrict__ centers, const float* __restrict__ sigmas){
    __shared__ float red[64];
    int r = blockIdx.x, tid = threadIdx.x;
    float p = 0.f;
    for (int i = tid; i < IN_D; i += 64){
        float c = centers[i*RU + r], sg = sigmas[i*RU + r];
        float s = HCONST/(sg*sg) + EPS_C;
        p += c*c*s;
    }
    red[tid] = p; __syncthreads();
    for (int s2 = 32; s2 > 0; s2 >>= 1){
        if (tid < s2) red[tid] += red[tid+s2];
        __syncthreads();
    }
    if (tid == 0) g_K2[r] = red[0];
}

// ---------------- k0_tail: tail weights + tail G/Bc ----------------
__global__ void k0_tail(const float* __restrict__ W, const float* __restrict__ gamma,
                        const float* __restrict__ beta){
    __shared__ float rg[4], rb[4];
    int o = blockIdx.x, t = threadIdx.x;
    int d = 32768 + t;
    float wv = W[(size_t)o*DDIM + d];
    float gv = gamma[d]*wv;
    float bv = beta[d]*wv;
    g_Wt[o*RU + t] = gv;
    #pragma unroll
    for (int off = 16; off; off >>= 1){
        gv += __shfl_down_sync(0xffffffffu, gv, off);
        bv += __shfl_down_sync(0xffffffffu, bv, off);
    }
    int lane = t & 31, w = t >> 5;
    if (lane == 0){ rg[w] = gv; rb[w] = bv; }
    __syncthreads();
    if (t == 0){
        atomicAdd(&g_G [o], rg[0]+rg[1]+rg[2]+rg[3]);
        atomicAdd(&g_Bc[o], rb[0]+rb[1]+rb[2]+rb[3]);
    }
}

// ---------------- k0_bsplit: coalesced B build ----------------
// grid (8 ic, 64 o), 256 thr. Block: one o, all 128 r, i-chunk of 32.
// Load coalesced W rows -> smem gw (pre-mul gamma); write 256B-coalesced word rows.
__global__ void k0_bsplit(const float* __restrict__ W, const float* __restrict__ gamma,
                          const float* __restrict__ beta){
    __shared__ float gw[128*33];
    __shared__ float rg[8], rb[8];
    const int ic = blockIdx.x, o = blockIdx.y;
    const int t = threadIdx.x, lane = t & 31, w = t >> 5;
    const int i0 = ic*32;
    float sg = 0.f, sb = 0.f;
    #pragma unroll
    for (int u = 0; u < 16; ++u){
        int e = t + u*256;
        int r = e >> 5, il = e & 31;
        int d = r*256 + i0 + il;
        float wv = W[(size_t)o*DDIM + d];
        float gv = gamma[d]*wv;
        gw[r*33 + il] = gv;
        sg += gv; sb += beta[d]*wv;
    }
    __syncthreads();
    #pragma unroll
    for (int u = 0; u < 8; ++u){
        int q = t + u*256;               // 2048 words
        int il = q >> 6, rp = q & 63;
        float a = gw[(2*rp  )*33 + il];
        float b = gw[(2*rp+1)*33 + il];
        unsigned hi, lo; split_pack(a, b, hi, lo);
        size_t idx = (size_t)(i0+il)*4096 + o*64 + rp;
        g_Bhi[idx] = hi;
        g_Blo[idx] = lo;
    }
    #pragma unroll
    for (int off = 16; off; off >>= 1){
        sg += __shfl_down_sync(0xffffffffu, sg, off);
        sb += __shfl_down_sync(0xffffffffu, sb, off);
    }
    if (lane == 0){ rg[w] = sg; rb[w] = sb; }
    __syncthreads();
    if (t == 0){
        float a = 0.f, b2 = 0.f;
        #pragma unroll
        for (int u = 0; u < 8; ++u){ a += rg[u]; b2 += rb[u]; }
        atomicAdd(&g_G[o], a); atomicAdd(&g_Bc[o], b2);
    }
}

// ---------------- k1: firing levels + softmax + closed-form LN stats ----------------
__global__ __launch_bounds__(128,4) void k1_frs(const float* __restrict__ X){
    extern __shared__ float sm1[];
    float* Xs = sm1;             // [256][9]
    float* Ss = sm1 + 256*9;     // [32][128]
    float* Cs = Ss  + 32*128;    // [32][128]
    __shared__ float K2s[RU];
    const int tid  = threadIdx.x;
    const int b0   = blockIdx.x * 8;
    const int lane = tid & 31, wg = tid >> 5;
    if (tid < RU) K2s[tid] = g_K2[tid];
    for (int q = tid; q < 8*64; q += 128){
        int bb = q >> 6, i4 = (q & 63)*4;
        float4 v = *(const float4*)(X + (size_t)(b0+bb)*IN_D + i4);
        Xs[(i4+0)*9+bb]=v.x; Xs[(i4+1)*9+bb]=v.y;
        Xs[(i4+2)*9+bb]=v.z; Xs[(i4+3)*9+bb]=v.w;
    }
    ull A1p[2][2], A2p[2][2];
    #pragma unroll
    for (int bi = 0; bi < 2; ++bi){
        A1p[bi][0]=0ull; A1p[bi][1]=0ull; A2p[bi][0]=0ull; A2p[bi][1]=0ull;
    }
    for (int c = 0; c < 8; ++c){
        __syncthreads();
        for (int q = tid; q < 32*32; q += 128){
            int row = q >> 5, col4 = (q & 31)*4;
            *(float4*)(Ss + row*RU + col4) = *(const float4*)(g_S  + (size_t)(c*32+row)*RU + col4);
            *(float4*)(Cs + row*RU + col4) = *(const float4*)(g_CS + (size_t)(c*32+row)*RU + col4);
        }
        __syncthreads();
        #pragma unroll 4
        for (int k = 0; k < 32; ++k){
            int i = c*32 + k;
            float x0 = Xs[i*9 + wg*2 + 0];
            float x1 = Xs[i*9 + wg*2 + 1];
            ull xx0 = pk2(x0*x0), xx1 = pk2(x1*x1);
            ull xp0 = pk2(x0),    xp1 = pk2(x1);
            #pragma unroll
            for (int jp = 0; jp < 2; ++jp){
                ull s2 = *(const ull*)(Ss + k*RU + 2*lane + 64*jp);
                ull c2 = *(const ull*)(Cs + k*RU + 2*lane + 64*jp);
                fma2(A1p[0][jp], xx0, s2); fma2(A1p[1][jp], xx1, s2);
                fma2(A2p[0][jp], xp0, c2); fma2(A2p[1][jp], xp1, c2);
            }
        }
    }
    #pragma unroll
    for (int bi = 0; bi < 2; ++bi){
        float sx = 0.f, sxx = 0.f;
        #pragma unroll
        for (int t = 0; t < 8; ++t){
            float x = Xs[(lane + 32*t)*9 + wg*2 + bi];
            sx += x; sxx += x*x;
        }
        #pragma unroll
        for (int off = 16; off; off >>= 1){
            sx  += __shfl_xor_sync(0xffffffffu, sx,  off);
            sxx += __shfl_xor_sync(0xffffffffu, sxx, off);
        }
        float lg[4], e[4];
        #pragma unroll
        for (int jp = 0; jp < 2; ++jp){
            float a1l,a1h,a2l,a2h;
            unpk(A1p[bi][jp], a1l, a1h);
            unpk(A2p[bi][jp], a2l, a2h);
            int r = 2*lane + 64*jp;
            lg[2*jp+0] = -(a1l - 2.f*a2l + K2s[r+0]) * (1.f/256.f);
            lg[2*jp+1] = -(a1h - 2.f*a2h + K2s[r+1]) * (1.f/256.f);
        }
        float m = fmaxf(fmaxf(lg[0],lg[1]), fmaxf(lg[2],lg[3]));
        #pragma unroll
        for (int off = 16; off; off >>= 1)
            m = fmaxf(m, __shfl_xor_sync(0xffffffffu, m, off));
        float se = 0.f, se2 = 0.f;
        #pragma unroll
        for (int j = 0; j < 4; ++j){ e[j] = __expf(lg[j]-m); se += e[j]; se2 += e[j]*e[j]; }
        #pragma unroll
        for (int off = 16; off; off >>= 1){
            se  += __shfl_xor_sync(0xffffffffu, se,  off);
            se2 += __shfl_xor_sync(0xffffffffu, se2, off);
        }
        float inv  = 1.f/se;
        float mu   = (sx + 1.f) * (1.f/(float)DDIM);
        float ef2  = se2*inv*inv*(sxx + 1.f) * (1.f/(float)DDIM);
        float rstd = rsqrtf(ef2 - mu*mu + LN_EPS_C);
        int b = b0 + wg*2 + bi;
        float fr = inv*rstd;
        #pragma unroll
        for (int jp = 0; jp < 2; ++jp){
            int r = 2*lane + 64*jp;
            g_fsT[(size_t)(r  )*NB + b] = e[2*jp+0]*fr;
            g_fsT[(size_t)(r+1)*NB + b] = e[2*jp+1]*fr;
        }
        if (lane == 0) g_c0[b] = -mu*rstd;
    }
}

// ---------------- k2: bf16 wmma GEMM, cp.async 2-stage pipeline, fused epilogue ----------------
#define A_LD 72
#define B_LD 136
#define R_AH 0u
#define R_AL 18432u
#define R_BH 36864u
#define R_BL 54272u
#define BUF_SZ 71680u
#define OFF_WT 143360u
#define OFF_RED 67584u      // partials overlay (after Ps region)
#define K2_SMEM 143872u

__global__ __launch_bounds__(256,1) void k2_wmma(const float* __restrict__ bias,
                                                 float* __restrict__ out){
    extern __shared__ __align__(16) char sm[];
    float* Wts = (float*)(sm + OFF_WT);
    float* Ps  = (float*)sm;                 // epilogue overlay [b + r*132]
    float* Red = (float*)(sm + OFF_RED);
    const unsigned base = smem_u32(sm);
    const int tid = threadIdx.x;
    const int b0  = blockIdx.x * 128;
    const int o   = blockIdx.y;
    const int w   = tid >> 5;
    const int mw  = w >> 1, nw = w & 1;

    if (tid < 128) Wts[tid] = g_Wt[o*RU + tid];

    // cp.async issue for chunk kc into buffer bufb (smem base offset)
    auto issue = [&](int kc, unsigned bufb){
        #pragma unroll
        for (int u = 0; u < 4; ++u){
            int q = tid + u*256;             // 1024: A rows
            int row = q >> 3, s = q & 7;
            const unsigned* sh = g_Xhi + (size_t)(b0+row)*128 + kc*32 + s*4;
            const unsigned* sl = g_Xlo + (size_t)(b0+row)*128 + kc*32 + s*4;
            cpa16(bufb + R_AH + row*144 + s*16, sh);
            cpa16(bufb + R_AL + row*144 + s*16, sl);
        }
        #pragma unroll
        for (int u = 0; u < 4; ++u){
            int q = tid + u*256;             // 1024: B rows
            int k = q >> 4, s = q & 15;
            const unsigned* sh = g_Bhi + (size_t)(kc*64+k)*4096 + o*64 + s*4;
            const unsigned* sl = g_Blo + (size_t)(kc*64+k)*4096 + o*64 + s*4;
            cpa16(bufb + R_BH + k*272 + s*16, sh);
            cpa16(bufb + R_BL + k*272 + s*16, sl);
        }
    };

    wmma::fragment<wmma::accumulator,16,16,16,float> acc[2][4];
    #pragma unroll
    for (int mt = 0; mt < 2; ++mt)
        #pragma unroll
        for (int nt = 0; nt < 4; ++nt) wmma::fill_fragment(acc[mt][nt], 0.f);

    issue(0, base); CPA_COMMIT();
    for (int kc = 0; kc < 4; ++kc){
        if (kc + 1 < 4){ issue(kc+1, base + ((kc+1)&1)*BUF_SZ); CPA_COMMIT(); CPA_WAIT1(); }
        else CPA_WAIT0();
        __syncthreads();
        const char* bufc = sm + (kc&1)*BUF_SZ;
        const __nv_bfloat16* Ah = (const __nv_bfloat16*)(bufc + R_AH);
        const __nv_bfloat16* Al = (const __nv_bfloat16*)(bufc + R_AL);
        const __nv_bfloat16* Bh = (const __nv_bfloat16*)(bufc + R_BH);
        const __nv_bfloat16* Bl = (const __nv_bfloat16*)(bufc + R_BL);
        #pragma unroll
        for (int ks = 0; ks < 4; ++ks){
            wmma::fragment<wmma::matrix_a,16,16,16,__nv_bfloat16,wmma::row_major> ah[2], al[2];
            #pragma unroll
            for (int mt = 0; mt < 2; ++mt){
                wmma::load_matrix_sync(ah[mt], Ah + (mw*32 + mt*16)*A_LD + ks*16, A_LD);
                wmma::load_matrix_sync(al[mt], Al + (mw*32 + mt*16)*A_LD + ks*16, A_LD);
            }
            #pragma unroll
            for (int nt = 0; nt < 4; ++nt){
                wmma::fragment<wmma::matrix_b,16,16,16,__nv_bfloat16,wmma::row_major> bh, bl;
                wmma::load_matrix_sync(bh, Bh + ks*16*B_LD + nw*64 + nt*16, B_LD);
                wmma::load_matrix_sync(bl, Bl + ks*16*B_LD + nw*64 + nt*16, B_LD);
                #pragma unroll
                for (int mt = 0; mt < 2; ++mt){
                    wmma::mma_sync(acc[mt][nt], ah[mt], bh, acc[mt][nt]);
                    wmma::mma_sync(acc[mt][nt], ah[mt], bl, acc[mt][nt]);
                    wmma::mma_sync(acc[mt][nt], al[mt], bh, acc[mt][nt]);
                }
            }
        }
        __syncthreads();
    }
    // stage P col-major: element (b_local, r) at Ps[b + r*132]
    #pragma unroll
    for (int mt = 0; mt < 2; ++mt)
        #pragma unroll
        for (int nt = 0; nt < 4; ++nt)
            wmma::store_matrix_sync(Ps + (mw*32 + mt*16) + (size_t)(nw*64 + nt*16)*132,
                                    acc[mt][nt], 132, wmma::mem_col_major);
    __syncthreads();
    {   // rule reduction: 256 threads, each half handles 64 r's for one b
        int half = tid >> 7, bl = tid & 127;
        int b = b0 + bl;
        float s0 = 0.f, s1 = 0.f, s2 = 0.f, s3 = 0.f;
        int rb0 = half*64;
        #pragma unroll 4
        for (int u = 0; u < 16; ++u){
            int r = rb0 + 4*u;
            s0 += g_fsT[(size_t)(r  )*NB + b] * (Ps[bl + (r  )*132] + Wts[r  ]);
            s1 += g_fsT[(size_t)(r+1)*NB + b] * (Ps[bl + (r+1)*132] + Wts[r+1]);
            s2 += g_fsT[(size_t)(r+2)*NB + b] * (Ps[bl + (r+2)*132] + Wts[r+2]);
            s3 += g_fsT[(size_t)(r+3)*NB + b] * (Ps[bl + (r+3)*132] + Wts[r+3]);
        }
        Red[tid] = (s0+s1)+(s2+s3);
    }
    __syncthreads();
    if (tid < 128){
        int b = b0 + tid;
        float v = Red[tid] + Red[tid+128];
        out[(size_t)b*OD + o] = v + g_c0[b]*g_G[o] + g_Bc[o] + bias[o];
    }
}

// ---------------- launch ----------------
extern "C" void kernel_launch(void* const* d_in, const int* in_sizes, int n_in,
                              void* d_out, int out_size){
    const float* X       = (const float*)d_in[0];
    const float* centers = (const float*)d_in[1];
    const float* sigmas  = (const float*)d_in[2];
    const float* gamma   = (const float*)d_in[3];
    const float* beta    = (const float*)d_in[4];
    const float* W       = (const float*)d_in[5];
    const float* bias    = (const float*)d_in[6];
    float* out = (float*)d_out;
    (void)in_sizes; (void)n_in; (void)out_size;

    cudaFuncSetAttribute(k1_frs,  cudaFuncAttributeMaxDynamicSharedMemorySize, 42112);
    cudaFuncSetAttribute(k2_wmma, cudaFuncAttributeMaxDynamicSharedMemorySize, K2_SMEM);

    k0a_prep <<<(NB*128 + 255)/256, 256>>>(centers, sigmas, X);   // 1
    k0_k2c   <<<RU, 64>>>(centers, sigmas);                        // 2
    k0_tail  <<<OD, 128>>>(W, gamma, beta);                        // 3
    k0_bsplit<<<dim3(8, 64), 256>>>(W, gamma, beta);               // 4
    k1_frs   <<<NB/8, 128, 42112>>>(X);                            // 5
    k2_wmma  <<<dim3(NB/128, OD), 256, K2_SMEM>>>(bias, out);      // 6 (profiled)
}